// round 9
// baseline (speedup 1.0000x reference)
#include <cuda_runtime.h>

#define DIM    768
#define NEXP   8
#define PARTS  16                     // threads cooperating per token (2x R7)
#define TOKS   4                      // tokens per thread (keeps LDS traffic at R7 level)
#define JITER  (DIM / (PARTS * 4))    // float4 steps per part = 12
#define TPB    128

// Packed fp32x2 math (Blackwell): one instruction, two fp32 FMAs.
__device__ __forceinline__ unsigned long long ffma2(unsigned long long a,
                                                    unsigned long long b,
                                                    unsigned long long c) {
    unsigned long long d;
    asm("fma.rn.f32x2 %0, %1, %2, %3;" : "=l"(d) : "l"(a), "l"(b), "l"(c));
    return d;
}
__device__ __forceinline__ unsigned long long fadd2(unsigned long long a,
                                                    unsigned long long b) {
    unsigned long long d;
    asm("add.rn.f32x2 %0, %1, %2;" : "=l"(d) : "l"(a), "l"(b));
    return d;
}

__global__ __launch_bounds__(TPB)
void Router_54932631716286_kernel(const float* __restrict__ x,
                                  const float* __restrict__ W,
                                  const float* __restrict__ b,
                                  float* __restrict__ out,
                                  int n_tokens)
{
    // W: 8 x 768 fp32 = 24 KB staged in smem. Both 16-lane halves of a warp
    // read the same i -> 256B unique per LDS.128 (2 wavefronts, 2-way bcast).
    __shared__ float4 sW4[NEXP * DIM / 4];
    __shared__ float  sb[NEXP];

    const float4* W4 = reinterpret_cast<const float4*>(W);
    for (int i = threadIdx.x; i < NEXP * DIM / 4; i += TPB) sW4[i] = W4[i];
    if (threadIdx.x < NEXP) sb[threadIdx.x] = b[threadIdx.x];
    __syncthreads();

    int gtid  = blockIdx.x * TPB + threadIdx.x;
    int group = gtid >> 4;            // 16 consecutive lanes share a 4-token group
    int part  = gtid & 15;
    int t0    = group * TOKS;

    if (t0 >= n_tokens) return;       // group-aligned exit (N % TOKS == 0 here)

    // Clamped per-token rows (safe for any N).
    int tr1 = (t0 + 1 < n_tokens) ? t0 + 1 : t0;
    int tr2 = (t0 + 2 < n_tokens) ? t0 + 2 : t0;
    int tr3 = (t0 + 3 < n_tokens) ? t0 + 3 : t0;

    const ulonglong2* xr0 = reinterpret_cast<const ulonglong2*>(x + (size_t)t0  * DIM);
    const ulonglong2* xr1 = reinterpret_cast<const ulonglong2*>(x + (size_t)tr1 * DIM);
    const ulonglong2* xr2 = reinterpret_cast<const ulonglong2*>(x + (size_t)tr2 * DIM);
    const ulonglong2* xr3 = reinterpret_cast<const ulonglong2*>(x + (size_t)tr3 * DIM);
    const ulonglong2* wp  = reinterpret_cast<const ulonglong2*>(sW4);

    unsigned long long acc[NEXP][TOKS];
#pragma unroll
    for (int e = 0; e < NEXP; e++)
#pragma unroll
        for (int t = 0; t < TOKS; t++) acc[e][t] = 0ull;

    // Prefetch next j's 4 loads ahead of this j's FMA chain.
    int i = part;
    ulonglong2 nx0 = xr0[i], nx1 = xr1[i], nx2 = xr2[i], nx3 = xr3[i];
#pragma unroll
    for (int j = 0; j < JITER; j++) {
        ulonglong2 x0 = nx0, x1 = nx1, x2 = nx2, x3 = nx3;
        if (j + 1 < JITER) {
            nx0 = xr0[i + PARTS];
            nx1 = xr1[i + PARTS];
            nx2 = xr2[i + PARTS];
            nx3 = xr3[i + PARTS];
        }
#pragma unroll
        for (int e = 0; e < NEXP; e++) {
            ulonglong2 wv = wp[e * (DIM / 4) + i];
            acc[e][0] = ffma2(x0.x, wv.x, ffma2(x0.y, wv.y, acc[e][0]));
            acc[e][1] = ffma2(x1.x, wv.x, ffma2(x1.y, wv.y, acc[e][1]));
            acc[e][2] = ffma2(x2.x, wv.x, ffma2(x2.y, wv.y, acc[e][2]));
            acc[e][3] = ffma2(x3.x, wv.x, ffma2(x3.y, wv.y, acc[e][3]));
        }
        i += PARTS;
    }

    // Reduce the 16 part-partials (consecutive lanes) via butterfly shuffles.
#pragma unroll
    for (int e = 0; e < NEXP; e++) {
#pragma unroll
        for (int t = 0; t < TOKS; t++) {
            unsigned long long v = acc[e][t];
            v = fadd2(v, __shfl_xor_sync(0xffffffffu, v, 1));
            v = fadd2(v, __shfl_xor_sync(0xffffffffu, v, 2));
            v = fadd2(v, __shfl_xor_sync(0xffffffffu, v, 4));
            v = fadd2(v, __shfl_xor_sync(0xffffffffu, v, 8));
            acc[e][t] = v;
        }
    }

    if (part != 0) return;

    // Epilogue: one lane per group -> softmax + top-2 for its 4 tokens.
    float4 gv[2], iv[2];
    float* gvf = reinterpret_cast<float*>(gv);
    float* ivf = reinterpret_cast<float*>(iv);

#pragma unroll
    for (int t = 0; t < TOKS; t++) {
        float logits[NEXP];
        float m = -1e30f;
#pragma unroll
        for (int e = 0; e < NEXP; e++) {
            float lo = __uint_as_float((unsigned)(acc[e][t] & 0xffffffffull));
            float hi = __uint_as_float((unsigned)(acc[e][t] >> 32));
            logits[e] = lo + hi + sb[e];
            m = fmaxf(m, logits[e]);
        }
        float g[NEXP], s = 0.f;
#pragma unroll
        for (int e = 0; e < NEXP; e++) { g[e] = __expf(logits[e] - m); s += g[e]; }
        float inv = 1.0f / s;
#pragma unroll
        for (int e = 0; e < NEXP; e++) g[e] *= inv;

        // Top-2, strict '>' keeps lowest index on ties (matches jax.lax.top_k).
        int i1 = 0; float g1 = g[0];
#pragma unroll
        for (int e = 1; e < NEXP; e++) if (g[e] > g1) { g1 = g[e]; i1 = e; }
        int i2 = -1; float g2 = -1e30f;
#pragma unroll
        for (int e = 0; e < NEXP; e++) if (e != i1 && g[e] > g2) { g2 = g[e]; i2 = e; }

        gvf[2 * t + 0] = g1;
        gvf[2 * t + 1] = g2;
        ivf[2 * t + 0] = (float)i1;
        ivf[2 * t + 1] = (float)i2;
    }

    // Output: [0,2N) top-2 gates, [2N,4N) indices as fp32 (exact integers).
    float* og = out + (size_t)t0 * 2;                       // 32B aligned (t0 % 4 == 0)
    float* oi = out + (size_t)2 * n_tokens + (size_t)t0 * 2;
    if (t0 + TOKS <= n_tokens) {
        reinterpret_cast<float4*>(og)[0] = gv[0];
        reinterpret_cast<float4*>(og)[1] = gv[1];
        reinterpret_cast<float4*>(oi)[0] = iv[0];
        reinterpret_cast<float4*>(oi)[1] = iv[1];
    } else {
        for (int t = 0; t < TOKS && t0 + t < n_tokens; t++) {
            og[2 * t + 0] = gvf[2 * t + 0];
            og[2 * t + 1] = gvf[2 * t + 1];
            oi[2 * t + 0] = ivf[2 * t + 0];
            oi[2 * t + 1] = ivf[2 * t + 1];
        }
    }
}

extern "C" void kernel_launch(void* const* d_in, const int* in_sizes, int n_in,
                              void* d_out, int out_size) {
    const float* x = (const float*)d_in[0];
    const float* W = (const float*)d_in[1];
    const float* b = (const float*)d_in[2];
    float* out = (float*)d_out;

    int n_tokens = in_sizes[0] / DIM;                  // 128*197 = 25216
    int groups   = (n_tokens + TOKS - 1) / TOKS;       // 6304
    int threads  = groups * PARTS;                     // 100864
    int blocks   = (threads + TPB - 1) / TPB;          // 788

    Router_54932631716286_kernel<<<blocks, TPB>>>(x, W, b, out, n_tokens);
}

// round 10
// speedup vs baseline: 1.1252x; 1.1252x over previous
#include <cuda_runtime.h>

#define DIM    768
#define NEXP   8
#define PARTS  8                      // threads cooperating per token
#define TOKS   8                      // tokens per thread: halves LDS + issue vs R7
#define JITER  (DIM / (PARTS * 4))    // float4 steps per part = 24
#define ROWQ   (DIM / 4)              // ulonglong2 stride between token rows = 48
#define TPB    64

// Packed fp32x2 math (Blackwell): one instruction, two fp32 FMAs.
__device__ __forceinline__ unsigned long long ffma2(unsigned long long a,
                                                    unsigned long long b,
                                                    unsigned long long c) {
    unsigned long long d;
    asm("fma.rn.f32x2 %0, %1, %2, %3;" : "=l"(d) : "l"(a), "l"(b), "l"(c));
    return d;
}
__device__ __forceinline__ unsigned long long fadd2(unsigned long long a,
                                                    unsigned long long b) {
    unsigned long long d;
    asm("add.rn.f32x2 %0, %1, %2;" : "=l"(d) : "l"(a), "l"(b));
    return d;
}

__global__ __launch_bounds__(TPB)
void Router_54932631716286_kernel(const float* __restrict__ x,
                                  const float* __restrict__ W,
                                  const float* __restrict__ b,
                                  float* __restrict__ out,
                                  int n_tokens)
{
    // W: 8 x 768 fp32 = 24 KB in smem. All 4 eight-lane groups of a warp read
    // the same i -> 128B unique per LDS.128 = 1 wavefront, conflict-free.
    __shared__ float4 sW4[NEXP * DIM / 4];
    __shared__ float  sb[NEXP];

    const float4* W4 = reinterpret_cast<const float4*>(W);
    for (int i = threadIdx.x; i < NEXP * DIM / 4; i += TPB) sW4[i] = W4[i];
    if (threadIdx.x < NEXP) sb[threadIdx.x] = b[threadIdx.x];
    __syncthreads();

    int gtid  = blockIdx.x * TPB + threadIdx.x;
    int group = gtid >> 3;            // 8 consecutive lanes share an 8-token group
    int part  = gtid & 7;
    int t0    = group * TOKS;

    if (t0 >= n_tokens) return;       // group-aligned warp exit

    // Base row pointer; token rows are consecutive (stride ROWQ ulonglong2).
    // Ragged tail handled by clamped per-token offsets.
    const ulonglong2* xp = reinterpret_cast<const ulonglong2*>(x) + (size_t)t0 * ROWQ;
    int roff[TOKS];
#pragma unroll
    for (int t = 0; t < TOKS; t++)
        roff[t] = ((t0 + t < n_tokens) ? t : 0) * ROWQ;

    const ulonglong2* wp = reinterpret_cast<const ulonglong2*>(sW4);

    unsigned long long acc[NEXP][TOKS];
#pragma unroll
    for (int e = 0; e < NEXP; e++)
#pragma unroll
        for (int t = 0; t < TOKS; t++) acc[e][t] = 0ull;

    // Prefetch next j's 8 independent LDG.128 ahead of this j's FMA chain.
    int i = part;
    ulonglong2 pf[TOKS];
#pragma unroll
    for (int t = 0; t < TOKS; t++) pf[t] = xp[roff[t] + i];

#pragma unroll
    for (int j = 0; j < JITER; j++) {
        ulonglong2 xv[TOKS];
#pragma unroll
        for (int t = 0; t < TOKS; t++) xv[t] = pf[t];
        if (j + 1 < JITER) {
#pragma unroll
            for (int t = 0; t < TOKS; t++) pf[t] = xp[roff[t] + i + PARTS];
        }
#pragma unroll
        for (int e = 0; e < NEXP; e++) {
            ulonglong2 wv = wp[e * (DIM / 4) + i];   // 1-wavefront broadcast
#pragma unroll
            for (int t = 0; t < TOKS; t++)
                acc[e][t] = ffma2(xv[t].x, wv.x, ffma2(xv[t].y, wv.y, acc[e][t]));
        }
        i += PARTS;
    }

    // Reduce the 8 part-partials (consecutive lanes) via butterfly shuffles.
#pragma unroll
    for (int e = 0; e < NEXP; e++) {
#pragma unroll
        for (int t = 0; t < TOKS; t++) {
            unsigned long long v = acc[e][t];
            v = fadd2(v, __shfl_xor_sync(0xffffffffu, v, 1));
            v = fadd2(v, __shfl_xor_sync(0xffffffffu, v, 2));
            v = fadd2(v, __shfl_xor_sync(0xffffffffu, v, 4));
            acc[e][t] = v;
        }
    }

    if (part != 0) return;

    // Epilogue: one lane per group -> softmax + top-2 for its 8 tokens.
    float4 gv[TOKS / 2], iv[TOKS / 2];
    float* gvf = reinterpret_cast<float*>(gv);
    float* ivf = reinterpret_cast<float*>(iv);

#pragma unroll
    for (int t = 0; t < TOKS; t++) {
        float logits[NEXP];
        float m = -1e30f;
#pragma unroll
        for (int e = 0; e < NEXP; e++) {
            float lo = __uint_as_float((unsigned)(acc[e][t] & 0xffffffffull));
            float hi = __uint_as_float((unsigned)(acc[e][t] >> 32));
            logits[e] = lo + hi + sb[e];
            m = fmaxf(m, logits[e]);
        }
        float g[NEXP], s = 0.f;
#pragma unroll
        for (int e = 0; e < NEXP; e++) { g[e] = __expf(logits[e] - m); s += g[e]; }
        float inv = 1.0f / s;
#pragma unroll
        for (int e = 0; e < NEXP; e++) g[e] *= inv;

        // Top-2, strict '>' keeps lowest index on ties (matches jax.lax.top_k).
        int i1 = 0; float g1 = g[0];
#pragma unroll
        for (int e = 1; e < NEXP; e++) if (g[e] > g1) { g1 = g[e]; i1 = e; }
        int i2 = -1; float g2 = -1e30f;
#pragma unroll
        for (int e = 0; e < NEXP; e++) if (e != i1 && g[e] > g2) { g2 = g[e]; i2 = e; }

        gvf[2 * t + 0] = g1;
        gvf[2 * t + 1] = g2;
        ivf[2 * t + 0] = (float)i1;
        ivf[2 * t + 1] = (float)i2;
    }

    // Output: [0,2N) top-2 gates, [2N,4N) indices as fp32 (exact integers).
    float* og = out + (size_t)t0 * 2;                       // 16B aligned
    float* oi = out + (size_t)2 * n_tokens + (size_t)t0 * 2;
    if (t0 + TOKS <= n_tokens) {
#pragma unroll
        for (int q = 0; q < TOKS / 2; q++) {
            reinterpret_cast<float4*>(og)[q] = gv[q];
            reinterpret_cast<float4*>(oi)[q] = iv[q];
        }
    } else {
        for (int t = 0; t < TOKS && t0 + t < n_tokens; t++) {
            og[2 * t + 0] = gvf[2 * t + 0];
            og[2 * t + 1] = gvf[2 * t + 1];
            oi[2 * t + 0] = ivf[2 * t + 0];
            oi[2 * t + 1] = ivf[2 * t + 1];
        }
    }
}

extern "C" void kernel_launch(void* const* d_in, const int* in_sizes, int n_in,
                              void* d_out, int out_size) {
    const float* x = (const float*)d_in[0];
    const float* W = (const float*)d_in[1];
    const float* b = (const float*)d_in[2];
    float* out = (float*)d_out;

    int n_tokens = in_sizes[0] / DIM;                  // 128*197 = 25216
    int groups   = (n_tokens + TOKS - 1) / TOKS;       // 3152
    int threads  = groups * PARTS;                     // 25216
    int blocks   = (threads + TPB - 1) / TPB;          // 394

    Router_54932631716286_kernel<<<blocks, TPB>>>(x, W, b, out, n_tokens);
}

// round 11
// speedup vs baseline: 1.1485x; 1.0207x over previous
#include <cuda_runtime.h>

#define DIM    768
#define NEXP   8
#define PARTS  8                      // threads cooperating per token
#define TOKS   4                      // tokens per thread (R7 ridge config)
#define JITER  (DIM / (PARTS * 4))    // float4 steps per part = 24
#define ROWQ   (DIM / 4)              // ulonglong2 stride between token rows = 48
#define TPB    128
#define PD     2                      // prefetch distance (8 LDG.128 in flight/warp)

// Packed fp32x2 math (Blackwell): one instruction, two fp32 FMAs.
__device__ __forceinline__ unsigned long long ffma2(unsigned long long a,
                                                    unsigned long long b,
                                                    unsigned long long c) {
    unsigned long long d;
    asm("fma.rn.f32x2 %0, %1, %2, %3;" : "=l"(d) : "l"(a), "l"(b), "l"(c));
    return d;
}
__device__ __forceinline__ unsigned long long fadd2(unsigned long long a,
                                                    unsigned long long b) {
    unsigned long long d;
    asm("add.rn.f32x2 %0, %1, %2;" : "=l"(d) : "l"(a), "l"(b));
    return d;
}

__global__ __launch_bounds__(TPB)
void Router_54932631716286_kernel(const float* __restrict__ x,
                                  const float* __restrict__ W,
                                  const float* __restrict__ b,
                                  float* __restrict__ out,
                                  int n_tokens)
{
    // W: 8 x 768 fp32 = 24 KB in smem. All 4 eight-lane groups of a warp read
    // the same i -> 128B unique per LDS.128 = 1 wavefront, conflict-free.
    __shared__ float4 sW4[NEXP * DIM / 4];
    __shared__ float  sb[NEXP];

    const float4* W4 = reinterpret_cast<const float4*>(W);
    for (int i = threadIdx.x; i < NEXP * DIM / 4; i += TPB) sW4[i] = W4[i];
    if (threadIdx.x < NEXP) sb[threadIdx.x] = b[threadIdx.x];
    __syncthreads();

    int gtid  = blockIdx.x * TPB + threadIdx.x;
    int group = gtid >> 3;            // 8 consecutive lanes share a 4-token group
    int part  = gtid & 7;
    int t0    = group * TOKS;

    if (t0 >= n_tokens) return;       // group-aligned warp exit

    // Base row pointer; clamped per-token row offsets (ragged-tail safe).
    const ulonglong2* xp = reinterpret_cast<const ulonglong2*>(x) + (size_t)t0 * ROWQ;
    int roff[TOKS];
#pragma unroll
    for (int t = 0; t < TOKS; t++)
        roff[t] = ((t0 + t < n_tokens) ? t : 0) * ROWQ;

    const ulonglong2* wp = reinterpret_cast<const ulonglong2*>(sW4);

    unsigned long long acc[NEXP][TOKS];
#pragma unroll
    for (int e = 0; e < NEXP; e++)
#pragma unroll
        for (int t = 0; t < TOKS; t++) acc[e][t] = 0ull;

    // Software pipeline, depth 2: 8 independent LDG.128 in flight per warp,
    // each load issued ~2 compute bodies (>=380 cyc) before first use.
    ulonglong2 pf0[TOKS], pf1[TOKS];
#pragma unroll
    for (int t = 0; t < TOKS; t++) pf0[t] = xp[roff[t] + part];
#pragma unroll
    for (int t = 0; t < TOKS; t++) pf1[t] = xp[roff[t] + part + PARTS];

#pragma unroll
    for (int j = 0; j < JITER; j++) {
        int i = part + j * PARTS;     // this body's float4 index (x and W agree)

        ulonglong2 xv[TOKS];
#pragma unroll
        for (int t = 0; t < TOKS; t++) xv[t] = pf0[t];
#pragma unroll
        for (int t = 0; t < TOKS; t++) pf0[t] = pf1[t];
        if (j + PD < JITER) {
            int ip = part + (j + PD) * PARTS;
#pragma unroll
            for (int t = 0; t < TOKS; t++) pf1[t] = xp[roff[t] + ip];
        }

#pragma unroll
        for (int e = 0; e < NEXP; e++) {
            ulonglong2 wv = wp[e * (DIM / 4) + i];   // 1-wavefront broadcast
#pragma unroll
            for (int t = 0; t < TOKS; t++)
                acc[e][t] = ffma2(xv[t].x, wv.x, ffma2(xv[t].y, wv.y, acc[e][t]));
        }
    }

    // Reduce the 8 part-partials (consecutive lanes) via butterfly shuffles.
#pragma unroll
    for (int e = 0; e < NEXP; e++) {
#pragma unroll
        for (int t = 0; t < TOKS; t++) {
            unsigned long long v = acc[e][t];
            v = fadd2(v, __shfl_xor_sync(0xffffffffu, v, 1));
            v = fadd2(v, __shfl_xor_sync(0xffffffffu, v, 2));
            v = fadd2(v, __shfl_xor_sync(0xffffffffu, v, 4));
            acc[e][t] = v;
        }
    }

    if (part != 0) return;

    // Epilogue: one lane per group -> softmax + top-2 for its 4 tokens.
    float4 gv[2], iv[2];
    float* gvf = reinterpret_cast<float*>(gv);
    float* ivf = reinterpret_cast<float*>(iv);

#pragma unroll
    for (int t = 0; t < TOKS; t++) {
        float logits[NEXP];
        float m = -1e30f;
#pragma unroll
        for (int e = 0; e < NEXP; e++) {
            float lo = __uint_as_float((unsigned)(acc[e][t] & 0xffffffffull));
            float hi = __uint_as_float((unsigned)(acc[e][t] >> 32));
            logits[e] = lo + hi + sb[e];
            m = fmaxf(m, logits[e]);
        }
        float g[NEXP], s = 0.f;
#pragma unroll
        for (int e = 0; e < NEXP; e++) { g[e] = __expf(logits[e] - m); s += g[e]; }
        float inv = 1.0f / s;
#pragma unroll
        for (int e = 0; e < NEXP; e++) g[e] *= inv;

        // Top-2, strict '>' keeps lowest index on ties (matches jax.lax.top_k).
        int i1 = 0; float g1 = g[0];
#pragma unroll
        for (int e = 1; e < NEXP; e++) if (g[e] > g1) { g1 = g[e]; i1 = e; }
        int i2 = -1; float g2 = -1e30f;
#pragma unroll
        for (int e = 0; e < NEXP; e++) if (e != i1 && g[e] > g2) { g2 = g[e]; i2 = e; }

        gvf[2 * t + 0] = g1;
        gvf[2 * t + 1] = g2;
        ivf[2 * t + 0] = (float)i1;
        ivf[2 * t + 1] = (float)i2;
    }

    // Output: [0,2N) top-2 gates, [2N,4N) indices as fp32 (exact integers).
    float* og = out + (size_t)t0 * 2;                       // 32B aligned (t0 % 4 == 0)
    float* oi = out + (size_t)2 * n_tokens + (size_t)t0 * 2;
    if (t0 + TOKS <= n_tokens) {
        reinterpret_cast<float4*>(og)[0] = gv[0];
        reinterpret_cast<float4*>(og)[1] = gv[1];
        reinterpret_cast<float4*>(oi)[0] = iv[0];
        reinterpret_cast<float4*>(oi)[1] = iv[1];
    } else {
        for (int t = 0; t < TOKS && t0 + t < n_tokens; t++) {
            og[2 * t + 0] = gvf[2 * t + 0];
            og[2 * t + 1] = gvf[2 * t + 1];
            oi[2 * t + 0] = ivf[2 * t + 0];
            oi[2 * t + 1] = ivf[2 * t + 1];
        }
    }
}

extern "C" void kernel_launch(void* const* d_in, const int* in_sizes, int n_in,
                              void* d_out, int out_size) {
    const float* x = (const float*)d_in[0];
    const float* W = (const float*)d_in[1];
    const float* b = (const float*)d_in[2];
    float* out = (float*)d_out;

    int n_tokens = in_sizes[0] / DIM;                  // 128*197 = 25216
    int groups   = (n_tokens + TOKS - 1) / TOKS;       // 6304
    int threads  = groups * PARTS;                     // 50432
    int blocks   = (threads + TPB - 1) / TPB;          // 394

    Router_54932631716286_kernel<<<blocks, TPB>>>(x, W, b, out, n_tokens);
}